// round 2
// baseline (speedup 1.0000x reference)
#include <cuda_runtime.h>

#define D   128
#define TM  64
#define GT  256
#define PAD 4
#define LDW (D + PAD)   // 132 floats: keeps float4 alignment, spreads banks

// Scratch tables (allocation-free: __device__ globals)
__device__ float g_Ktab[50000 * D];   // tanh((attr + item) @ Wk^T + bk)
__device__ float g_A   [50000 * D];   // item @ Wv^T
__device__ float g_B   [ 5000 * D];   // opin @ Wv^T + bv
__device__ float g_Q   [10000 * D];   // tanh(user @ Wq^T + bq)

// out[m][n] = act( sum_k (X[m][k] + pre[k]) * W[n][k] + bias[n] )
// Register-blocked: 256 threads, 64-row tile, full N=K=128 in shared memory.
template<bool PRE, bool BIAS, bool TANH>
__global__ void __launch_bounds__(GT) gemm128(
    const float* __restrict__ X, const float* __restrict__ W,
    const float* __restrict__ bias, const float* __restrict__ pre,
    float* __restrict__ out, int M)
{
    extern __shared__ float smem[];
    float* As = smem;              // [TM][LDW]
    float* Ws = smem + TM * LDW;   // [D][LDW]

    const int tid  = threadIdx.x;
    const int row0 = blockIdx.x * TM;

    // Stage W [n][k] into shared (row-major, padded rows)
    #pragma unroll
    for (int idx = tid; idx < D * (D / 4); idx += GT) {
        int n = idx >> 5, kq = idx & 31;
        float4 w4 = *(const float4*)(W + (size_t)n * D + kq * 4);
        *(float4*)(Ws + n * LDW + kq * 4) = w4;
    }
    // Stage X tile (+pre broadcast vector)
    #pragma unroll
    for (int idx = tid; idx < TM * (D / 4); idx += GT) {
        int m = idx >> 5, kq = idx & 31;
        int gm = row0 + m;
        float4 x4 = make_float4(0.f, 0.f, 0.f, 0.f);
        if (gm < M) x4 = *(const float4*)(X + (size_t)gm * D + kq * 4);
        if (PRE) {
            float4 p4 = *(const float4*)(pre + kq * 4);
            x4.x += p4.x; x4.y += p4.y; x4.z += p4.z; x4.w += p4.w;
        }
        *(float4*)(As + m * LDW + kq * 4) = x4;
    }
    __syncthreads();

    const int tx = tid & 15;   // n dimension (cols n = tx + 16*j)
    const int ty = tid >> 4;   // m dimension (rows m = ty*4 + r)

    float acc[4][8];
    #pragma unroll
    for (int r = 0; r < 4; r++)
        #pragma unroll
        for (int j = 0; j < 8; j++) acc[r][j] = 0.f;

    #pragma unroll 4
    for (int k0 = 0; k0 < D; k0 += 4) {
        float4 a4[4];
        #pragma unroll
        for (int r = 0; r < 4; r++)
            a4[r] = *(const float4*)(As + (ty * 4 + r) * LDW + k0);
        #pragma unroll
        for (int j = 0; j < 8; j++) {
            float4 w4 = *(const float4*)(Ws + (tx + 16 * j) * LDW + k0);
            #pragma unroll
            for (int r = 0; r < 4; r++) {
                acc[r][j] += a4[r].x * w4.x;
                acc[r][j] += a4[r].y * w4.y;
                acc[r][j] += a4[r].z * w4.z;
                acc[r][j] += a4[r].w * w4.w;
            }
        }
    }

    #pragma unroll
    for (int r = 0; r < 4; r++) {
        int gm = row0 + ty * 4 + r;
        if (gm >= M) continue;
        #pragma unroll
        for (int j = 0; j < 8; j++) {
            int n = tx + 16 * j;
            float v = acc[r][j];
            if (BIAS) v += __ldg(bias + n);
            if (TANH) v = tanhf(v);
            out[(size_t)gm * D + n] = v;
        }
    }
}

// One warp per user: w_l = (i_l>0) * (Q[u] . Ktab[i_l]);
// out[u] = sum_l w_l * tanh(A[i_l] + B[o_l])
__global__ void __launch_bounds__(256) attend_kernel(
    const int* __restrict__ item_seqs,
    const int* __restrict__ opin_seqs,
    float* __restrict__ out, int U, int L)
{
    int gw   = (int)((blockIdx.x * blockDim.x + threadIdx.x) >> 5);
    int lane = threadIdx.x & 31;
    if (gw >= U) return;

    const float4 q = *(const float4*)(g_Q + (size_t)gw * D + lane * 4);
    float4 acc = make_float4(0.f, 0.f, 0.f, 0.f);

    const int* is = item_seqs + (size_t)gw * L;
    const int* os = opin_seqs + (size_t)gw * L;

    #pragma unroll 2
    for (int l = 0; l < L; ++l) {
        int i = __ldg(is + l);
        if (i > 0) {  // warp-uniform branch (same i for all lanes)
            int o = __ldg(os + l);
            const float4 kv = *(const float4*)(g_Ktab + (size_t)i * D + lane * 4);
            float w = q.x * kv.x + q.y * kv.y + q.z * kv.z + q.w * kv.w;
            #pragma unroll
            for (int s = 16; s; s >>= 1)
                w += __shfl_xor_sync(0xffffffffu, w, s);
            float4 a4 = *(const float4*)(g_A + (size_t)i * D + lane * 4);
            float4 b4 = *(const float4*)(g_B + (size_t)o * D + lane * 4);
            acc.x += w * tanhf(a4.x + b4.x);
            acc.y += w * tanhf(a4.y + b4.y);
            acc.z += w * tanhf(a4.z + b4.z);
            acc.w += w * tanhf(a4.w + b4.w);
        }
    }
    *(float4*)(out + (size_t)gw * D + lane * 4) = acc;
}

extern "C" void kernel_launch(void* const* d_in, const int* in_sizes, int n_in,
                              void* d_out, int out_size)
{
    const float* item_table = (const float*)d_in[0];
    const float* opin_table = (const float*)d_in[1];
    const float* user_emb   = (const float*)d_in[2];
    const float* attr       = (const float*)d_in[3];
    const float* Wq         = (const float*)d_in[4];
    const float* bq         = (const float*)d_in[5];
    const float* Wk         = (const float*)d_in[6];
    const float* bk         = (const float*)d_in[7];
    const float* Wv         = (const float*)d_in[8];
    const float* bv         = (const float*)d_in[9];
    const int*   item_seqs  = (const int*)d_in[10];
    const int*   opin_seqs  = (const int*)d_in[11];
    float*       out        = (float*)d_out;

    const int n_item = in_sizes[0] / D;
    const int n_opi  = in_sizes[1] / D;
    const int U      = in_sizes[2] / D;
    const int L      = in_sizes[10] / U;

    float *pK, *pA, *pB, *pQ;
    cudaGetSymbolAddress((void**)&pK, g_Ktab);
    cudaGetSymbolAddress((void**)&pA, g_A);
    cudaGetSymbolAddress((void**)&pB, g_B);
    cudaGetSymbolAddress((void**)&pQ, g_Q);

    const size_t smemB = (size_t)(TM + D) * LDW * sizeof(float);  // ~99 KB
    cudaFuncSetAttribute((const void*)gemm128<true,  true,  true >,
                         cudaFuncAttributeMaxDynamicSharedMemorySize, (int)smemB);
    cudaFuncSetAttribute((const void*)gemm128<false, false, false>,
                         cudaFuncAttributeMaxDynamicSharedMemorySize, (int)smemB);
    cudaFuncSetAttribute((const void*)gemm128<false, true,  false>,
                         cudaFuncAttributeMaxDynamicSharedMemorySize, (int)smemB);
    cudaFuncSetAttribute((const void*)gemm128<false, true,  true >,
                         cudaFuncAttributeMaxDynamicSharedMemorySize, (int)smemB);

    // Ktab[i] = tanh((attr + item[i]) @ Wk^T + bk)
    gemm128<true, true, true><<<(n_item + TM - 1) / TM, GT, smemB>>>(
        item_table, Wk, bk, attr, pK, n_item);
    // A[i] = item[i] @ Wv^T
    gemm128<false, false, false><<<(n_item + TM - 1) / TM, GT, smemB>>>(
        item_table, Wv, nullptr, nullptr, pA, n_item);
    // B[o] = opin[o] @ Wv^T + bv
    gemm128<false, true, false><<<(n_opi + TM - 1) / TM, GT, smemB>>>(
        opin_table, Wv, bv, nullptr, pB, n_opi);
    // Q[u] = tanh(user[u] @ Wq^T + bq)
    gemm128<false, true, true><<<(U + TM - 1) / TM, GT, smemB>>>(
        user_emb, Wq, bq, nullptr, pQ, U);

    // Attention/aggregation pass: one warp per user
    const int threads = 256;
    const int blocks  = (U * 32 + threads - 1) / threads;
    attend_kernel<<<blocks, threads>>>(item_seqs, opin_seqs, out, U, L);
}

// round 3
// speedup vs baseline: 1.0363x; 1.0363x over previous
#include <cuda_runtime.h>
#include <cuda_fp16.h>
#include <cstdint>

#define D      128
#define LDH    136            // half row stride in smem (8-half pad -> 4-bank skew)
#define GEMM_T 256            // threads per GEMM CTA (8 warps)

// fp16 scratch tables (allocation-free __device__ globals)
__device__ __half g_Ktab[50000 * D];   // tanh((attr + item) @ Wk^T + bk)
__device__ __half g_A   [50000 * D];   // item @ Wv^T
__device__ __half g_B   [ 5000 * D];   // opin @ Wv^T + bv
__device__ __half g_Q   [10000 * D];   // tanh(user @ Wq^T + bq)

static __device__ __forceinline__ uint32_t smem_u32(const void* p) {
    return (uint32_t)__cvta_generic_to_shared(p);
}

static __device__ __forceinline__ void ldsm_x4(uint32_t& r0, uint32_t& r1,
                                               uint32_t& r2, uint32_t& r3, uint32_t addr) {
    asm volatile("ldmatrix.sync.aligned.m8n8.x4.shared.b16 {%0,%1,%2,%3}, [%4];"
                 : "=r"(r0), "=r"(r1), "=r"(r2), "=r"(r3) : "r"(addr));
}
static __device__ __forceinline__ void ldsm_x2(uint32_t& r0, uint32_t& r1, uint32_t addr) {
    asm volatile("ldmatrix.sync.aligned.m8n8.x2.shared.b16 {%0,%1}, [%2];"
                 : "=r"(r0), "=r"(r1) : "r"(addr));
}
static __device__ __forceinline__ void mma16816(float& d0, float& d1, float& d2, float& d3,
                                                uint32_t a0, uint32_t a1, uint32_t a2, uint32_t a3,
                                                uint32_t b0, uint32_t b1) {
    asm volatile("mma.sync.aligned.m16n8k16.row.col.f32.f16.f16.f32 "
                 "{%0,%1,%2,%3}, {%4,%5,%6,%7}, {%8,%9}, {%0,%1,%2,%3};"
                 : "+f"(d0), "+f"(d1), "+f"(d2), "+f"(d3)
                 : "r"(a0), "r"(a1), "r"(a2), "r"(a3), "r"(b0), "r"(b1));
}

// out[m][n] = act( sum_k (X[m][k] (+ pre[k])) * W[n][k] (+ bias[n]) ), fp16 output.
// Tensor-core tf(fp16) hi/lo 3-pass for ~fp32 accuracy. CTA tile 128x128, K=128.
template<bool PRE, bool BIAS, bool TANH>
__global__ void __launch_bounds__(GEMM_T) gemm_mma(
    const float* __restrict__ X, const float* __restrict__ W,
    const float* __restrict__ bias, const float* __restrict__ pre,
    __half* __restrict__ out, int M)
{
    extern __shared__ __half sm[];
    __half* Xhi = sm;
    __half* Xlo = Xhi + 128 * LDH;
    __half* Whi = Xlo + 128 * LDH;
    __half* Wlo = Whi + 128 * LDH;

    const int tid  = threadIdx.x;
    const int row0 = blockIdx.x * 128;

    // Stage X tile: fp32 -> hi/lo fp16 split (PRE folded before split)
    #pragma unroll 4
    for (int idx = tid; idx < 128 * 128; idx += GEMM_T) {
        int m = idx >> 7, k = idx & 127;
        int gm = row0 + m;
        float v = (gm < M) ? X[(size_t)gm * D + k] : 0.f;
        if (PRE) v += __ldg(pre + k);
        __half hi = __float2half_rn(v);
        __half lo = __float2half_rn(v - __half2float(hi));
        Xhi[m * LDH + k] = hi;
        Xlo[m * LDH + k] = lo;
    }
    // Stage W (full 128x128): hi/lo split
    #pragma unroll 4
    for (int idx = tid; idx < 128 * 128; idx += GEMM_T) {
        int n = idx >> 7, k = idx & 127;
        float v = W[(size_t)n * D + k];
        __half hi = __float2half_rn(v);
        __half lo = __float2half_rn(v - __half2float(hi));
        Whi[n * LDH + k] = hi;
        Wlo[n * LDH + k] = lo;
    }
    __syncthreads();

    const int lane = tid & 31;
    const int wid  = tid >> 5;
    const int wm   = wid >> 1;   // 0..3 -> 32-row band
    const int wn   = wid & 1;    // 0..1 -> 64-col band

    // ldmatrix source addresses (k0 = 0 bases; advance by 32B per k-step)
    // A (x4): groups g = lane>>3: tiles (m0-7,k0),(m8-15,k0),(m0-7,k0+8),(m8-15,k0+8)
    const int ag    = lane >> 3;
    const int arow  = wm * 32 + (ag & 1) * 8 + (lane & 7);
    const int acol  = (ag >> 1) * 8;
    uint32_t aHiBase[2], aLoBase[2];
    #pragma unroll
    for (int mf = 0; mf < 2; mf++) {
        aHiBase[mf] = smem_u32(Xhi + (arow + mf * 16) * LDH + acol);
        aLoBase[mf] = smem_u32(Xlo + (arow + mf * 16) * LDH + acol);
    }
    // B (x2): threads 0-15: tiles (n0-7,k0),(n0-7,k0+8); rows are W's n rows
    const int bg   = (lane >> 3) & 1;
    const int brow = wn * 64 + (lane & 7);
    const int bcol = bg * 8;
    const uint32_t bHiBase = smem_u32(Whi + brow * LDH + bcol);
    const uint32_t bLoBase = smem_u32(Wlo + brow * LDH + bcol);

    float acc[2][8][4];
    #pragma unroll
    for (int mf = 0; mf < 2; mf++)
        #pragma unroll
        for (int nf = 0; nf < 8; nf++)
            #pragma unroll
            for (int c = 0; c < 4; c++) acc[mf][nf][c] = 0.f;

    #pragma unroll
    for (int ks = 0; ks < 8; ks++) {          // k0 = ks*16
        const uint32_t koff = ks * 16 * sizeof(__half);
        uint32_t ahi[2][4], alo[2][4];
        #pragma unroll
        for (int mf = 0; mf < 2; mf++) {
            ldsm_x4(ahi[mf][0], ahi[mf][1], ahi[mf][2], ahi[mf][3], aHiBase[mf] + koff);
            ldsm_x4(alo[mf][0], alo[mf][1], alo[mf][2], alo[mf][3], aLoBase[mf] + koff);
        }
        uint32_t bhi[8][2], blo[8][2];
        #pragma unroll
        for (int nf = 0; nf < 8; nf++) {
            const uint32_t noff = nf * 8 * LDH * sizeof(__half);
            ldsm_x2(bhi[nf][0], bhi[nf][1], bHiBase + noff + koff);
            ldsm_x2(blo[nf][0], blo[nf][1], bLoBase + noff + koff);
        }
        #pragma unroll
        for (int nf = 0; nf < 8; nf++)
            #pragma unroll
            for (int mf = 0; mf < 2; mf++) {
                mma16816(acc[mf][nf][0], acc[mf][nf][1], acc[mf][nf][2], acc[mf][nf][3],
                         ahi[mf][0], ahi[mf][1], ahi[mf][2], ahi[mf][3],
                         bhi[nf][0], bhi[nf][1]);
                mma16816(acc[mf][nf][0], acc[mf][nf][1], acc[mf][nf][2], acc[mf][nf][3],
                         ahi[mf][0], ahi[mf][1], ahi[mf][2], ahi[mf][3],
                         blo[nf][0], blo[nf][1]);
                mma16816(acc[mf][nf][0], acc[mf][nf][1], acc[mf][nf][2], acc[mf][nf][3],
                         alo[mf][0], alo[mf][1], alo[mf][2], alo[mf][3],
                         bhi[nf][0], bhi[nf][1]);
            }
    }

    // Epilogue: bias, tanh, fp16 store
    #pragma unroll
    for (int mf = 0; mf < 2; mf++) {
        const int r0 = row0 + wm * 32 + mf * 16 + (lane >> 2);
        const int r1 = r0 + 8;
        #pragma unroll
        for (int nf = 0; nf < 8; nf++) {
            const int col = wn * 64 + nf * 8 + 2 * (lane & 3);
            float v0 = acc[mf][nf][0], v1 = acc[mf][nf][1];
            float v2 = acc[mf][nf][2], v3 = acc[mf][nf][3];
            if (BIAS) {
                float b0 = __ldg(bias + col), b1 = __ldg(bias + col + 1);
                v0 += b0; v1 += b1; v2 += b0; v3 += b1;
            }
            if (TANH) { v0 = tanhf(v0); v1 = tanhf(v1); v2 = tanhf(v2); v3 = tanhf(v3); }
            if (r0 < M) *(__half2*)(out + (size_t)r0 * D + col) = __floats2half2_rn(v0, v1);
            if (r1 < M) *(__half2*)(out + (size_t)r1 * D + col) = __floats2half2_rn(v2, v3);
        }
    }
}

// One warp per user: w_l = (i_l>0) * (Q[u] . Ktab[i_l]);
// out[u] = sum_l w_l * tanh(A[i_l] + B[o_l])   (tables fp16, math fp32)
__global__ void __launch_bounds__(256) attend_kernel(
    const int* __restrict__ item_seqs,
    const int* __restrict__ opin_seqs,
    float* __restrict__ out, int U, int L)
{
    const int gw   = (int)((blockIdx.x * blockDim.x + threadIdx.x) >> 5);
    const int lane = threadIdx.x & 31;
    if (gw >= U) return;

    // lane covers cols [lane*4, lane*4+4)
    uint2 qw = *(const uint2*)(g_Q + (size_t)gw * D + lane * 4);
    float2 q01 = __half22float2(*reinterpret_cast<__half2*>(&qw.x));
    float2 q23 = __half22float2(*reinterpret_cast<__half2*>(&qw.y));

    float4 acc = make_float4(0.f, 0.f, 0.f, 0.f);
    const int* is = item_seqs + (size_t)gw * L;
    const int* os = opin_seqs + (size_t)gw * L;

    #pragma unroll 2
    for (int l = 0; l < L; ++l) {
        int i = __ldg(is + l);
        if (i > 0) {   // warp-uniform
            int o = __ldg(os + l);
            uint2 kw = *(const uint2*)(g_Ktab + (size_t)i * D + lane * 4);
            float2 k01 = __half22float2(*reinterpret_cast<__half2*>(&kw.x));
            float2 k23 = __half22float2(*reinterpret_cast<__half2*>(&kw.y));
            float w = q01.x * k01.x + q01.y * k01.y + q23.x * k23.x + q23.y * k23.y;
            #pragma unroll
            for (int s = 16; s; s >>= 1)
                w += __shfl_xor_sync(0xffffffffu, w, s);
            uint2 aw = *(const uint2*)(g_A + (size_t)i * D + lane * 4);
            uint2 bw = *(const uint2*)(g_B + (size_t)o * D + lane * 4);
            float2 a01 = __half22float2(*reinterpret_cast<__half2*>(&aw.x));
            float2 a23 = __half22float2(*reinterpret_cast<__half2*>(&aw.y));
            float2 b01 = __half22float2(*reinterpret_cast<__half2*>(&bw.x));
            float2 b23 = __half22float2(*reinterpret_cast<__half2*>(&bw.y));
            acc.x += w * tanhf(a01.x + b01.x);
            acc.y += w * tanhf(a01.y + b01.y);
            acc.z += w * tanhf(a23.x + b23.x);
            acc.w += w * tanhf(a23.y + b23.y);
        }
    }
    *(float4*)(out + (size_t)gw * D + lane * 4) = acc;
}

extern "C" void kernel_launch(void* const* d_in, const int* in_sizes, int n_in,
                              void* d_out, int out_size)
{
    const float* item_table = (const float*)d_in[0];
    const float* opin_table = (const float*)d_in[1];
    const float* user_emb   = (const float*)d_in[2];
    const float* attr       = (const float*)d_in[3];
    const float* Wq         = (const float*)d_in[4];
    const float* bq         = (const float*)d_in[5];
    const float* Wk         = (const float*)d_in[6];
    const float* bk         = (const float*)d_in[7];
    const float* Wv         = (const float*)d_in[8];
    const float* bv         = (const float*)d_in[9];
    const int*   item_seqs  = (const int*)d_in[10];
    const int*   opin_seqs  = (const int*)d_in[11];
    float*       out        = (float*)d_out;

    const int n_item = in_sizes[0] / D;
    const int n_opi  = in_sizes[1] / D;
    const int U      = in_sizes[2] / D;
    const int L      = in_sizes[10] / U;

    __half *pK, *pA, *pB, *pQ;
    cudaGetSymbolAddress((void**)&pK, g_Ktab);
    cudaGetSymbolAddress((void**)&pA, g_A);
    cudaGetSymbolAddress((void**)&pB, g_B);
    cudaGetSymbolAddress((void**)&pQ, g_Q);

    const int smemB = 4 * 128 * LDH * sizeof(__half);   // ~139 KB
    cudaFuncSetAttribute((const void*)gemm_mma<true,  true,  true >,
                         cudaFuncAttributeMaxDynamicSharedMemorySize, smemB);
    cudaFuncSetAttribute((const void*)gemm_mma<false, false, false>,
                         cudaFuncAttributeMaxDynamicSharedMemorySize, smemB);
    cudaFuncSetAttribute((const void*)gemm_mma<false, true,  false>,
                         cudaFuncAttributeMaxDynamicSharedMemorySize, smemB);
    cudaFuncSetAttribute((const void*)gemm_mma<false, true,  true >,
                         cudaFuncAttributeMaxDynamicSharedMemorySize, smemB);

    // Ktab[i] = tanh((attr + item[i]) @ Wk^T + bk)
    gemm_mma<true, true, true><<<(n_item + 127) / 128, GEMM_T, smemB>>>(
        item_table, Wk, bk, attr, pK, n_item);
    // A[i] = item[i] @ Wv^T
    gemm_mma<false, false, false><<<(n_item + 127) / 128, GEMM_T, smemB>>>(
        item_table, Wv, nullptr, nullptr, pA, n_item);
    // B[o] = opin[o] @ Wv^T + bv
    gemm_mma<false, true, false><<<(n_opi + 127) / 128, GEMM_T, smemB>>>(
        opin_table, Wv, bv, nullptr, pB, n_opi);
    // Q[u] = tanh(user[u] @ Wq^T + bq)
    gemm_mma<false, true, true><<<(U + 127) / 128, GEMM_T, smemB>>>(
        user_emb, Wq, bq, nullptr, pQ, U);

    // Attention/aggregation pass: one warp per user
    const int threads = 256;
    const int blocks  = (U * 32 + threads - 1) / threads;
    attend_kernel<<<blocks, threads>>>(item_seqs, opin_seqs, out, U, L);
}